// round 6
// baseline (speedup 1.0000x reference)
#include <cuda_runtime.h>

#define POOL 7
#define FW 128
#define FC 1024
#define CG (FC / 4)          // 256 float4 channel-groups per pixel
#define TPB 128              // each thread handles 2 channel groups

__device__ __forceinline__ float4 bilin4(float4 tl, float4 tr, float4 bl, float4 br,
                                         float fx, float fy) {
    float4 o;
    float top, bot;
    top = tl.x + (tr.x - tl.x) * fx;
    bot = bl.x + (br.x - bl.x) * fx;
    o.x = top + (bot - top) * fy;
    top = tl.y + (tr.y - tl.y) * fx;
    bot = bl.y + (br.y - bl.y) * fx;
    o.y = top + (bot - top) * fy;
    top = tl.z + (tr.z - tl.z) * fx;
    bot = bl.z + (br.z - bl.z) * fx;
    o.z = top + (bot - top) * fy;
    top = tl.w + (tr.w - tl.w) * fx;
    bot = bl.w + (br.w - bl.w) * fx;
    o.w = top + (bot - top) * fy;
    return o;
}

__global__ __launch_bounds__(TPB, 12)
void roi_bilinear_kernel(const float* __restrict__ feat,
                         const float* __restrict__ rois,
                         float* __restrict__ out) {
    const int px  = blockIdx.x;           // 0..6
    const int py  = blockIdx.y;           // 0..6
    const int roi = blockIdx.z;           // 0..511

    const float4 r = __ldg(((const float4*)rois) + roi);
    const int ymin = (int)r.x;
    const int xmin = (int)r.y;
    const int ymax = (int)r.z;
    const int xmax = (int)r.w;

    const float h = (float)(ymax - ymin + 1);
    const float w = (float)(xmax - xmin + 1);

    const float sy = (float)py * (h / (float)POOL);
    const float sx = (float)px * (w / (float)POOL);

    const int y0 = (int)floorf(sy);
    const int x0 = (int)floorf(sx);
    const int y1 = min(y0 + 1, ymax - ymin);
    const int x1 = min(x0 + 1, xmax - xmin);

    const float fy = sy - (float)y0;
    const float fx = sx - (float)x0;

    // Warp-uniform: right column / bottom row contribute nothing when the
    // lerp factor is exactly 0 or the coordinate is clamped to a duplicate.
    const bool needx = (x1 != x0) && (fx != 0.0f);
    const bool needy = (y1 != y0) && (fy != 0.0f);

    const int gy0 = ymin + y0;
    const int gy1 = ymin + y1;
    const int gx0 = xmin + x0;
    const int gx1 = xmin + x1;

    const float4* __restrict__ featv = (const float4*)feat;
    const size_t b00 = ((size_t)gy0 * FW + gx0) * CG;
    const size_t b01 = ((size_t)gy0 * FW + gx1) * CG;
    const size_t b10 = ((size_t)gy1 * FW + gx0) * CG;
    const size_t b11 = ((size_t)gy1 * FW + gx1) * CG;

    const int c0 = threadIdx.x;          // groups c0 and c0+128
    const int c1 = threadIdx.x + TPB;

    // Always-needed top-left pair
    const float4 tl0 = __ldg(featv + b00 + c0);
    const float4 tl1 = __ldg(featv + b00 + c1);

    // Conditionally loaded corners (warp-uniform predicates, no divergence;
    // predicated-off loads consume no L1 wavefronts / L2 bytes)
    float4 tr0 = tl0, tr1 = tl1;
    if (needx) {
        tr0 = __ldg(featv + b01 + c0);
        tr1 = __ldg(featv + b01 + c1);
    }
    float4 bl0 = tl0, bl1 = tl1;
    if (needy) {
        bl0 = __ldg(featv + b10 + c0);
        bl1 = __ldg(featv + b10 + c1);
    }
    float4 br0, br1;
    if (needx && needy) {
        br0 = __ldg(featv + b11 + c0);
        br1 = __ldg(featv + b11 + c1);
    } else if (needy) {       // !needx: br column == bl column
        br0 = bl0; br1 = bl1;
    } else if (needx) {       // !needy: br row == tr row
        br0 = tr0; br1 = tr1;
    } else {
        br0 = tl0; br1 = tl1;
    }

    const float4 o0 = bilin4(tl0, tr0, bl0, br0, fx, fy);
    const float4 o1 = bilin4(tl1, tr1, bl1, br1, fx, fy);

    const int cell = py * POOL + px;
    float4* __restrict__ outv =
        (float4*)(out + ((size_t)roi * (POOL * POOL) + cell) * FC);
    outv[c0] = o0;
    outv[c1] = o1;
}

extern "C" void kernel_launch(void* const* d_in, const int* in_sizes, int n_in,
                              void* d_out, int out_size) {
    const float* feat = (const float*)d_in[0];   // (1,128,128,1024) fp32
    const float* rois = (const float*)d_in[1];   // (512,4) fp32
    float* out = (float*)d_out;                  // (512, 7*7*1024) fp32

    dim3 grid(POOL, POOL, 512);
    roi_bilinear_kernel<<<grid, TPB>>>(feat, rois, out);
}

// round 8
// speedup vs baseline: 1.0049x; 1.0049x over previous
#include <cuda_runtime.h>

#define POOL 7
#define FW 128
#define FC 1024
#define CG8 (FC / 8)         // 128 8-float groups per pixel
#define TPB 128

struct f8 { float4 a, b; };

// 32-byte feature load: non-coherent, L2 evict_last (pin feat map in L2)
__device__ __forceinline__ f8 ldg_el(const float* __restrict__ p) {
    unsigned long long x0, x1, x2, x3;
    asm("ld.global.nc.L2::evict_last.v4.b64 {%0,%1,%2,%3}, [%4];"
        : "=l"(x0), "=l"(x1), "=l"(x2), "=l"(x3)
        : "l"(p));
    f8 v;
    v.a.x = __uint_as_float((unsigned)(x0));
    v.a.y = __uint_as_float((unsigned)(x0 >> 32));
    v.a.z = __uint_as_float((unsigned)(x1));
    v.a.w = __uint_as_float((unsigned)(x1 >> 32));
    v.b.x = __uint_as_float((unsigned)(x2));
    v.b.y = __uint_as_float((unsigned)(x2 >> 32));
    v.b.z = __uint_as_float((unsigned)(x3));
    v.b.w = __uint_as_float((unsigned)(x3 >> 32));
    return v;
}

__device__ __forceinline__ float4 bilin4(float4 tl, float4 tr, float4 bl, float4 br,
                                         float fx, float fy) {
    float4 o;
    float top, bot;
    top = tl.x + (tr.x - tl.x) * fx;
    bot = bl.x + (br.x - bl.x) * fx;
    o.x = top + (bot - top) * fy;
    top = tl.y + (tr.y - tl.y) * fx;
    bot = bl.y + (br.y - bl.y) * fx;
    o.y = top + (bot - top) * fy;
    top = tl.z + (tr.z - tl.z) * fx;
    bot = bl.z + (br.z - bl.z) * fx;
    o.z = top + (bot - top) * fy;
    top = tl.w + (tr.w - tl.w) * fx;
    bot = bl.w + (br.w - bl.w) * fx;
    o.w = top + (bot - top) * fy;
    return o;
}

__global__ __launch_bounds__(TPB, 10)
void roi_bilinear_kernel(const float* __restrict__ feat,
                         const float* __restrict__ rois,
                         float* __restrict__ out) {
    const int px  = blockIdx.x;           // 0..6
    const int py  = blockIdx.y;           // 0..6
    const int roi = blockIdx.z;           // 0..511

    const float4 r = __ldg(((const float4*)rois) + roi);
    const int ymin = (int)r.x;
    const int xmin = (int)r.y;
    const int ymax = (int)r.z;
    const int xmax = (int)r.w;

    const float h = (float)(ymax - ymin + 1);
    const float w = (float)(xmax - xmin + 1);

    const float sy = (float)py * (h / (float)POOL);
    const float sx = (float)px * (w / (float)POOL);

    const int y0 = (int)floorf(sy);
    const int x0 = (int)floorf(sx);
    const int y1 = min(y0 + 1, ymax - ymin);
    const int x1 = min(x0 + 1, xmax - xmin);

    const float fy = sy - (float)y0;
    const float fx = sx - (float)x0;

    // Warp-uniform dead-load elimination
    const bool needx = (x1 != x0) && (fx != 0.0f);
    const bool needy = (y1 != y0) && (fy != 0.0f);

    const int gy0 = ymin + y0;
    const int gy1 = ymin + y1;
    const int gx0 = xmin + x0;
    const int gx1 = xmin + x1;

    const int c = threadIdx.x;            // 8-float group 0..127
    const size_t coff = (size_t)c * 8;

    const float* __restrict__ p00 = feat + ((size_t)gy0 * FW + gx0) * FC + coff;
    const float* __restrict__ p01 = feat + ((size_t)gy0 * FW + gx1) * FC + coff;
    const float* __restrict__ p10 = feat + ((size_t)gy1 * FW + gx0) * FC + coff;
    const float* __restrict__ p11 = feat + ((size_t)gy1 * FW + gx1) * FC + coff;

    const f8 tl = ldg_el(p00);

    f8 tr = tl;
    if (needx) tr = ldg_el(p01);
    f8 bl = tl;
    if (needy) bl = ldg_el(p10);
    f8 br;
    if (needx && needy) br = ldg_el(p11);
    else if (needy)     br = bl;
    else if (needx)     br = tr;
    else                br = tl;

    const float4 o0 = bilin4(tl.a, tr.a, bl.a, br.a, fx, fy);
    const float4 o1 = bilin4(tl.b, tr.b, bl.b, br.b, fx, fy);

    const int cell = py * POOL + px;
    float4* __restrict__ outv =
        (float4*)(out + ((size_t)roi * (POOL * POOL) + cell) * FC + coff);
    __stcs(outv,     o0);   // streaming store: don't pollute L2
    __stcs(outv + 1, o1);
}

extern "C" void kernel_launch(void* const* d_in, const int* in_sizes, int n_in,
                              void* d_out, int out_size) {
    const float* feat = (const float*)d_in[0];   // (1,128,128,1024) fp32
    const float* rois = (const float*)d_in[1];   // (512,4) fp32
    float* out = (float*)d_out;                  // (512, 7*7*1024) fp32

    dim3 grid(POOL, POOL, 512);
    roi_bilinear_kernel<<<grid, TPB>>>(feat, rois, out);
}

// round 9
// speedup vs baseline: 1.0429x; 1.0379x over previous
#include <cuda_runtime.h>

#define POOL 7
#define FW 128
#define FC 1024
#define CG (FC / 4)      // 256 float4 groups per pixel
#define TPB 128
#define RCHUNK 8         // rois per CTA
#define NBUF 3

__device__ __forceinline__ void cpa16(float4* smem_dst, const float4* gmem_src, bool pred) {
    if (pred) {
        unsigned s = (unsigned)__cvta_generic_to_shared(smem_dst);
        asm volatile("cp.async.cg.shared.global [%0], [%1], 16;\n" :: "r"(s), "l"(gmem_src));
    }
}

struct Geom {
    int p00, p01, p10, p11;   // pixel indices (y*FW+x)
    float fx, fy;
    bool nx, ny;
};

__device__ __forceinline__ Geom geom(const float* __restrict__ rois, int roi, int py, int px) {
    const float4 r = __ldg(((const float4*)rois) + roi);
    const int ymin = (int)r.x;
    const int xmin = (int)r.y;
    const int ymax = (int)r.z;
    const int xmax = (int)r.w;

    const float h = (float)(ymax - ymin + 1);
    const float w = (float)(xmax - xmin + 1);
    const float sy = (float)py * (h / (float)POOL);
    const float sx = (float)px * (w / (float)POOL);

    const int y0 = (int)floorf(sy);
    const int x0 = (int)floorf(sx);
    const int y1 = min(y0 + 1, ymax - ymin);
    const int x1 = min(x0 + 1, xmax - xmin);

    Geom g;
    g.fy = sy - (float)y0;
    g.fx = sx - (float)x0;
    g.nx = (x1 != x0) && (g.fx != 0.0f);
    g.ny = (y1 != y0) && (g.fy != 0.0f);
    const int gy0 = ymin + y0, gy1 = ymin + y1;
    const int gx0 = xmin + x0, gx1 = xmin + x1;
    g.p00 = gy0 * FW + gx0;
    g.p01 = gy0 * FW + gx1;
    g.p10 = gy1 * FW + gx0;
    g.p11 = gy1 * FW + gx1;
    return g;
}

__device__ __forceinline__ float4 bilin4(float4 tl, float4 tr, float4 bl, float4 br,
                                         float fx, float fy) {
    float4 o;
    float top, bot;
    top = tl.x + (tr.x - tl.x) * fx;
    bot = bl.x + (br.x - bl.x) * fx;
    o.x = top + (bot - top) * fy;
    top = tl.y + (tr.y - tl.y) * fx;
    bot = bl.y + (br.y - bl.y) * fx;
    o.y = top + (bot - top) * fy;
    top = tl.z + (tr.z - tl.z) * fx;
    bot = bl.z + (br.z - bl.z) * fx;
    o.z = top + (bot - top) * fy;
    top = tl.w + (tr.w - tl.w) * fx;
    bot = bl.w + (br.w - bl.w) * fx;
    o.w = top + (bot - top) * fy;
    return o;
}

__global__ __launch_bounds__(TPB, 4)
void roi_pipe_kernel(const float* __restrict__ feat,
                     const float* __restrict__ rois,
                     float* __restrict__ out) {
    // thread-private chunks: thread t writes/reads only [k][t] and [k][t+128]
    __shared__ float4 buf[NBUF][4][CG];          // 48 KB

    const int cell  = blockIdx.x;                // 0..48
    const int rbase = blockIdx.y * RCHUNK;       // 0,8,...,504
    const int py = cell / POOL;
    const int px = cell % POOL;
    const int tid = threadIdx.x;

    const float4* __restrict__ featv = (const float4*)feat;

    // ---- issue stage: predicated corner copies into buf[s] ----
    auto issue = [&](int i, int s) {
        const Geom g = geom(rois, rbase + i, py, px);
        const float4* s00 = featv + (size_t)g.p00 * CG;
        const float4* s01 = featv + (size_t)g.p01 * CG;
        const float4* s10 = featv + (size_t)g.p10 * CG;
        const float4* s11 = featv + (size_t)g.p11 * CG;
        cpa16(&buf[s][0][tid],       s00 + tid,       true);
        cpa16(&buf[s][0][tid + 128], s00 + tid + 128, true);
        cpa16(&buf[s][1][tid],       s01 + tid,       g.nx);
        cpa16(&buf[s][1][tid + 128], s01 + tid + 128, g.nx);
        cpa16(&buf[s][2][tid],       s10 + tid,       g.ny);
        cpa16(&buf[s][2][tid + 128], s10 + tid + 128, g.ny);
        cpa16(&buf[s][3][tid],       s11 + tid,       g.nx && g.ny);
        cpa16(&buf[s][3][tid + 128], s11 + tid + 128, g.nx && g.ny);
        asm volatile("cp.async.commit_group;\n" ::: "memory");
    };

    // ---- compute stage ----
    auto compute = [&](int i, int s) {
        const Geom g = geom(rois, rbase + i, py, px);
        const float4 tl0 = buf[s][0][tid];
        const float4 tl1 = buf[s][0][tid + 128];
        float4 tr0 = tl0, tr1 = tl1;
        if (g.nx) { tr0 = buf[s][1][tid]; tr1 = buf[s][1][tid + 128]; }
        float4 bl0 = tl0, bl1 = tl1;
        if (g.ny) { bl0 = buf[s][2][tid]; bl1 = buf[s][2][tid + 128]; }
        float4 br0, br1;
        if (g.nx && g.ny) { br0 = buf[s][3][tid]; br1 = buf[s][3][tid + 128]; }
        else if (g.ny)    { br0 = bl0; br1 = bl1; }
        else if (g.nx)    { br0 = tr0; br1 = tr1; }
        else              { br0 = tl0; br1 = tl1; }

        const float4 o0 = bilin4(tl0, tr0, bl0, br0, g.fx, g.fy);
        const float4 o1 = bilin4(tl1, tr1, bl1, br1, g.fx, g.fy);

        float4* __restrict__ outv =
            (float4*)(out + ((size_t)(rbase + i) * (POOL * POOL) + cell) * FC);
        __stcs(outv + tid,       o0);
        __stcs(outv + tid + 128, o1);
    };

    // ---- software pipeline over RCHUNK rois, depth 2, 3 buffers ----
    issue(0, 0);
    issue(1, 1);
    #pragma unroll
    for (int i = 0; i < RCHUNK; ++i) {
        if (i < RCHUNK - 1) {
            asm volatile("cp.async.wait_group 1;\n" ::: "memory");
        } else {
            asm volatile("cp.async.wait_group 0;\n" ::: "memory");
        }
        compute(i, i % NBUF);
        if (i + 2 < RCHUNK) issue(i + 2, (i + 2) % NBUF);
    }
}

extern "C" void kernel_launch(void* const* d_in, const int* in_sizes, int n_in,
                              void* d_out, int out_size) {
    const float* feat = (const float*)d_in[0];   // (1,128,128,1024) fp32
    const float* rois = (const float*)d_in[1];   // (512,4) fp32
    float* out = (float*)d_out;                  // (512, 7*7*1024) fp32

    dim3 grid(POOL * POOL, 512 / RCHUNK);        // 49 x 64
    roi_pipe_kernel<<<grid, TPB>>>(feat, rois, out);
}